// round 9
// baseline (speedup 1.0000x reference)
#include <cuda_runtime.h>
#include <cstdint>

#define BB      8
#define CTOT    256
#define HH      96
#define WW      128
#define TH      2                  // output rows per block (warp covers both)
#define ROWT    (HH/TH)            // 48
#define CCK     2                  // channels per chunk
#define NCHUNK  (CTOT/CCK)         // 128
#define NBUF    5                  // ring buffers
#define DEPTH   4                  // prefetch distance (chunks)
#define THREADS 288                // 9 warps, one dy each
#define CHS     (HH*WW)            // channel stride (floats)

#define ROWB       640                         // bytes per halo row (544 used; 128-mult)
#define CH_SEG     (TH*ROWB)                   // 1280 (2 rows per channel)
#define WARP_SEG   (CCK*CH_SEG)                // 2560 per warp per buffer
#define BUF_BYTES  (9*WARP_SEG)                // 23040
#define SMEM_TOTAL (NBUF*BUF_BYTES)            // 115200 -> 2 blocks/SM

typedef unsigned long long ull;

// 16B-chunk swizzle: kills the 2-way conflict of 32B-stride LDS.128 lanes.
__device__ __host__ __forceinline__ uint32_t swz16(uint32_t a) {
    return a ^ ((a >> 3) & 0x10u);
}

__device__ __forceinline__ float4 lds128(uint32_t addr) {
    float4 v;
    asm volatile("ld.shared.v4.f32 {%0,%1,%2,%3}, [%4];"
                 : "=f"(v.x), "=f"(v.y), "=f"(v.z), "=f"(v.w) : "r"(addr));
    return v;
}
__device__ __forceinline__ void sts_zero16(uint32_t addr) {
    asm volatile("st.shared.v4.b32 [%0], {%1,%1,%1,%1};" :: "r"(addr), "r"(0) : "memory");
}
__device__ __forceinline__ void cpa16(uint32_t dst, const float* src) {
    asm volatile("cp.async.cg.shared.global [%0], [%1], 16;" :: "r"(dst), "l"(src));
}
__device__ __forceinline__ ull pk(float lo, float hi) {
    ull r;
    asm("mov.b64 %0, {%1,%2};" : "=l"(r) : "f"(lo), "f"(hi));
    return r;
}
__device__ __forceinline__ float2 upk(ull v) {
    float2 f;
    asm("mov.b64 {%0,%1}, %2;" : "=f"(f.x), "=f"(f.y) : "l"(v));
    return f;
}
__device__ __forceinline__ void ffma2(ull& d, ull a, ull b) {
    asm("fma.rn.f32x2 %0, %1, %2, %0;" : "+l"(d) : "l"(a), "l"(b));
}

// Warp-private loader: lane's half-warp row (r), chunks g+1 and g+17, CCK channels.
__device__ __forceinline__ void load_chunk(uint32_t wbuf, const float* src,
                                           uint32_t offW0, uint32_t offW1,
                                           int g, bool rowOK)
{
    if (rowOK) {
#pragma unroll
        for (int c = 0; c < CCK; c++) {
            const float* s = src + (size_t)c * CHS + 4 * g;
            cpa16(wbuf + c * CH_SEG + offW0, s);
            cpa16(wbuf + c * CH_SEG + offW1, s + 64);
        }
    }
    asm volatile("cp.async.commit_group;" ::: "memory");
}

__device__ __forceinline__ void compute_chunk(uint32_t wbuf, const float* pA,
                                              const uint32_t* offR, ull acc[9][4])
{
#pragma unroll
    for (int c = 0; c < CCK; c++) {
        const float* a = pA + (size_t)c * CHS;
        float4 qa0 = __ldg((const float4*)a);
        float4 qa1 = __ldg((const float4*)(a + 4));
        const uint32_t rb = wbuf + c * CH_SEG;
        float4 q0 = lds128(rb + offR[0]);
        float4 q1 = lds128(rb + offR[1]);
        float4 q2 = lds128(rb + offR[2]);
        float4 q3 = lds128(rb + offR[3]);

        ull A[4];
        A[0] = pk(qa0.x, qa0.y); A[1] = pk(qa0.z, qa0.w);
        A[2] = pk(qa1.x, qa1.y); A[3] = pk(qa1.z, qa1.w);

        // E pairs are quad halves (register-pair free); O pairs straddle.
        ull E[8], O[7];
        E[0] = pk(q0.x, q0.y); E[1] = pk(q0.z, q0.w);
        E[2] = pk(q1.x, q1.y); E[3] = pk(q1.z, q1.w);
        E[4] = pk(q2.x, q2.y); E[5] = pk(q2.z, q2.w);
        E[6] = pk(q3.x, q3.y); E[7] = pk(q3.z, q3.w);
        O[0] = pk(q0.y, q0.z); O[1] = pk(q0.w, q1.x);
        O[2] = pk(q1.y, q1.z); O[3] = pk(q1.w, q2.x);
        O[4] = pk(q2.y, q2.z); O[5] = pk(q2.w, q3.x);
        O[6] = pk(q3.y, q3.z);

#pragma unroll
        for (int d = 0; d < 9; d++) {
#pragma unroll
            for (int t = 0; t < 4; t++) {
                ull bo = (d & 1) ? O[t + (d >> 1)] : E[t + (d >> 1)];
                ffma2(acc[d][t], A[t], bo);
            }
        }
    }
}

__global__ void __launch_bounds__(THREADS, 2)
corr_kernel(const float* __restrict__ in1, const float* __restrict__ in2,
            float* __restrict__ out)
{
    extern __shared__ char smem[];
    const uint32_t smem32 = (uint32_t)__cvta_generic_to_shared(smem);

    const int tid  = threadIdx.x;
    const int warp = tid >> 5;         // dy 0..8
    const int lane = tid & 31;
    const int r    = lane >> 4;        // row within tile (0/1)
    const int g    = lane & 15;        // 8-px group
    const int x0   = g << 3;

    const int bx = blockIdx.x;
    const int b  = bx / ROWT;
    const int h0 = (bx - b * ROWT) * TH;

    const int hB = h0 + r + warp - 4;  // this lane's in2 source row
    const bool rowOK = (hB >= 0) && (hB < HH);

    // Swizzled per-lane offsets (within a channel segment)
    uint32_t offR[4];
#pragma unroll
    for (int j = 0; j < 4; j++)
        offR[j] = (uint32_t)(r * ROWB) + swz16((uint32_t)(32 * g + 16 * j));
    const uint32_t offW0 = (uint32_t)(r * ROWB) + swz16((uint32_t)(16 * (g + 1)));
    const uint32_t offW1 = (uint32_t)(r * ROWB) + swz16((uint32_t)(16 * (g + 17)));

    const uint32_t wbBase = smem32 + (uint32_t)(warp * WARP_SEG);
    const uint32_t wbEnd  = wbBase + SMEM_TOTAL;

    // Lane-local pre-zero of pads / OOB windows across the whole ring.
#pragma unroll
    for (int buf = 0; buf < NBUF; buf++) {
#pragma unroll
        for (int c = 0; c < CCK; c++) {
            const uint32_t rb = wbBase + buf * BUF_BYTES + c * CH_SEG;
            if (!rowOK) {
#pragma unroll
                for (int j = 0; j < 4; j++) sts_zero16(rb + offR[j]);
            } else {
                if (g == 0)  sts_zero16(rb + r * ROWB);        // left pad (chunk 0)
                if (g == 15) sts_zero16(rb + r * ROWB + 528);  // right pad (chunk 33)
            }
        }
    }
    __syncwarp();

    const float* pAc = in1 + (size_t)(b * CTOT) * CHS + (h0 + r) * WW + x0;
    const float* sp  = in2 + (size_t)(b * CTOT) * CHS + (rowOK ? hB : 0) * WW;
    const size_t CSTEP = (size_t)CCK * CHS;

    ull acc[9][4];
#pragma unroll
    for (int d = 0; d < 9; d++)
#pragma unroll
        for (int t = 0; t < 4; t++) acc[d][t] = 0ull;

    // Prologue: fill DEPTH buffers
    uint32_t wbNxt = wbBase;
#pragma unroll
    for (int i = 0; i < DEPTH; i++) {
        load_chunk(wbNxt, sp, offW0, offW1, g, rowOK);
        sp += CSTEP;
        wbNxt += BUF_BYTES;
    }
    uint32_t wbCur = wbBase;

    for (int k = 0; k < NCHUNK; k++) {
        if (k + DEPTH < NCHUNK) {
            load_chunk(wbNxt, sp, offW0, offW1, g, rowOK);
            sp += CSTEP;
            wbNxt += BUF_BYTES;
            if (wbNxt >= wbEnd) wbNxt -= SMEM_TOTAL;
            asm volatile("cp.async.wait_group 4;" ::: "memory");
        } else if (k + 3 < NCHUNK) {
            asm volatile("cp.async.wait_group 3;" ::: "memory");
        } else if (k + 2 < NCHUNK) {
            asm volatile("cp.async.wait_group 2;" ::: "memory");
        } else if (k + 1 < NCHUNK) {
            asm volatile("cp.async.wait_group 1;" ::: "memory");
        } else {
            asm volatile("cp.async.wait_group 0;" ::: "memory");
        }
        compute_chunk(wbCur, pAc, offR, acc);
        pAc += CSTEP;
        wbCur += BUF_BYTES;
        if (wbCur >= wbEnd) wbCur -= SMEM_TOTAL;
    }

    // Epilogue: out[b, warp*9+d, h0+r, x0..x0+7] = acc / 256
    const float inv = 1.0f / 256.0f;
    const int hOut = h0 + r;
#pragma unroll
    for (int d = 0; d < 9; d++) {
        const int n = warp * 9 + d;
        float* op = out + ((size_t)((b * 81 + n) * HH + hOut)) * WW + x0;
        float2 u0 = upk(acc[d][0]);
        float2 u1 = upk(acc[d][1]);
        float2 u2 = upk(acc[d][2]);
        float2 u3 = upk(acc[d][3]);
        *(float4*)op       = make_float4(u0.x * inv, u0.y * inv, u1.x * inv, u1.y * inv);
        *(float4*)(op + 4) = make_float4(u2.x * inv, u2.y * inv, u3.x * inv, u3.y * inv);
    }
}

extern "C" void kernel_launch(void* const* d_in, const int* in_sizes, int n_in,
                              void* d_out, int out_size)
{
    const float* in1 = (const float*)d_in[0];
    const float* in2 = (const float*)d_in[1];
    float* out = (float*)d_out;

    cudaFuncSetAttribute(corr_kernel, cudaFuncAttributeMaxDynamicSharedMemorySize, SMEM_TOTAL);
    corr_kernel<<<BB * ROWT, THREADS, SMEM_TOTAL>>>(in1, in2, out);
}

// round 10
// speedup vs baseline: 1.4639x; 1.4639x over previous
#include <cuda_runtime.h>
#include <cstdint>

#define BB      8
#define CTOT    256
#define HH      96
#define WW      128
#define THREADS 288                // 9 warps, one dy each
#define CHS     (HH*WW)            // channel stride (floats)
#define CHS4    (CHS/4)            // channel stride (float4)

typedef unsigned long long ull;

__device__ __forceinline__ ull pk(float lo, float hi) {
    ull r;
    asm("mov.b64 %0, {%1,%2};" : "=l"(r) : "f"(lo), "f"(hi));
    return r;
}
__device__ __forceinline__ float2 upk(ull v) {
    float2 f;
    asm("mov.b64 {%0,%1}, %2;" : "=f"(f.x), "=f"(f.y) : "l"(v));
    return f;
}
__device__ __forceinline__ void ffma2(ull& d, ull a, ull b) {
    asm("fma.rn.f32x2 %0, %1, %2, %0;" : "+l"(d) : "l"(a), "l"(b));
}

__global__ void __launch_bounds__(THREADS, 2)
corr_kernel(const float* __restrict__ in1, const float* __restrict__ in2,
            float* __restrict__ out)
{
    const int tid  = threadIdx.x;
    const int warp = tid >> 5;         // dy 0..8
    const int lane = tid & 31;
    const int x0   = lane << 2;        // 4 px per lane

    const int bx = blockIdx.x;
    const int b  = bx / HH;
    const int h0 = bx - b * HH;        // output row

    const int hB = h0 + warp - 4;      // this warp's in2 source row
    const bool rowOK = (hB >= 0) && (hB < HH);   // warp-uniform

    ull acc[9][2];
#pragma unroll
    for (int d = 0; d < 9; d++) { acc[d][0] = 0ull; acc[d][1] = 0ull; }

    if (rowOK) {
        const float4* pA = (const float4*)(in1 + (size_t)(b * CTOT) * CHS + h0 * WW + x0);
        const float4* pB = (const float4*)(in2 + (size_t)(b * CTOT) * CHS + hB * WW + x0);

#pragma unroll 2
        for (int c = 0; c < CTOT; c++) {
            float4 a = __ldg(pA + (size_t)c * CHS4);
            float4 m = __ldg(pB + (size_t)c * CHS4);

            // Halo quads from neighbor lanes (shuffle network, no smem).
            float4 qL, qR;
            qL.x = __shfl_up_sync(0xffffffffu, m.x, 1);
            qL.y = __shfl_up_sync(0xffffffffu, m.y, 1);
            qL.z = __shfl_up_sync(0xffffffffu, m.z, 1);
            qL.w = __shfl_up_sync(0xffffffffu, m.w, 1);
            qR.x = __shfl_down_sync(0xffffffffu, m.x, 1);
            qR.y = __shfl_down_sync(0xffffffffu, m.y, 1);
            qR.z = __shfl_down_sync(0xffffffffu, m.z, 1);
            qR.w = __shfl_down_sync(0xffffffffu, m.w, 1);
            if (lane == 0)  { qL.x = 0.f; qL.y = 0.f; qL.z = 0.f; qL.w = 0.f; }
            if (lane == 31) { qR.x = 0.f; qR.y = 0.f; qR.z = 0.f; qR.w = 0.f; }

            ull A0 = pk(a.x, a.y);
            ull A1 = pk(a.z, a.w);

            // f[0..11] = in2[x0-4 .. x0+7] = qL | m | qR
            ull E[6], O[5];
            E[0] = pk(qL.x, qL.y); E[1] = pk(qL.z, qL.w);
            E[2] = pk(m.x,  m.y ); E[3] = pk(m.z,  m.w );
            E[4] = pk(qR.x, qR.y); E[5] = pk(qR.z, qR.w);
            O[0] = pk(qL.y, qL.z); O[1] = pk(qL.w, m.x );
            O[2] = pk(m.y,  m.z ); O[3] = pk(m.w,  qR.x);
            O[4] = pk(qR.y, qR.z);

#pragma unroll
            for (int d = 0; d < 9; d++) {
                ull b0 = (d & 1) ? O[(d >> 1)]     : E[(d >> 1)];
                ull b1 = (d & 1) ? O[(d >> 1) + 1] : E[(d >> 1) + 1];
                ffma2(acc[d][0], A0, b0);
                ffma2(acc[d][1], A1, b1);
            }
        }
    }

    // Epilogue: out[b, warp*9+d, h0, x0..x0+3] = acc / 256  (zeros when !rowOK)
    const float inv = 1.0f / 256.0f;
#pragma unroll
    for (int d = 0; d < 9; d++) {
        const int n = warp * 9 + d;
        float* op = out + ((size_t)((b * 81 + n) * HH + h0)) * WW + x0;
        float2 u0 = upk(acc[d][0]);
        float2 u1 = upk(acc[d][1]);
        *(float4*)op = make_float4(u0.x * inv, u0.y * inv, u1.x * inv, u1.y * inv);
    }
}

extern "C" void kernel_launch(void* const* d_in, const int* in_sizes, int n_in,
                              void* d_out, int out_size)
{
    const float* in1 = (const float*)d_in[0];
    const float* in2 = (const float*)d_in[1];
    float* out = (float*)d_out;

    corr_kernel<<<BB * HH, THREADS>>>(in1, in2, out);
}

// round 11
// speedup vs baseline: 2.1444x; 1.4649x over previous
#include <cuda_runtime.h>
#include <cstdint>

#define BB      8
#define CTOT    256
#define HH      96
#define WW      128
#define THREADS 288                // 9 warps, one dy each
#define CHS     (HH*WW)            // channel stride (floats)
#define CHS4    (CHS/4)            // channel stride (float4)

typedef unsigned long long ull;

__device__ __forceinline__ ull pk(float lo, float hi) {
    ull r;
    asm("mov.b64 %0, {%1,%2};" : "=l"(r) : "f"(lo), "f"(hi));
    return r;
}
__device__ __forceinline__ float2 upk(ull v) {
    float2 f;
    asm("mov.b64 {%0,%1}, %2;" : "=f"(f.x), "=f"(f.y) : "l"(v));
    return f;
}
__device__ __forceinline__ void ffma2(ull& d, ull a, ull b) {
    asm("fma.rn.f32x2 %0, %1, %2, %0;" : "+l"(d) : "l"(a), "l"(b));
}

// One channel: halo exchange via shuffles, then 18 packed FMAs.
__device__ __forceinline__ void compute_channel(float4 a, float4 m, int lane,
                                                ull acc[9][2])
{
    float4 qL, qR;
    qL.x = __shfl_up_sync(0xffffffffu, m.x, 1);
    qL.y = __shfl_up_sync(0xffffffffu, m.y, 1);
    qL.z = __shfl_up_sync(0xffffffffu, m.z, 1);
    qL.w = __shfl_up_sync(0xffffffffu, m.w, 1);
    qR.x = __shfl_down_sync(0xffffffffu, m.x, 1);
    qR.y = __shfl_down_sync(0xffffffffu, m.y, 1);
    qR.z = __shfl_down_sync(0xffffffffu, m.z, 1);
    qR.w = __shfl_down_sync(0xffffffffu, m.w, 1);
    if (lane == 0)  { qL.x = 0.f; qL.y = 0.f; qL.z = 0.f; qL.w = 0.f; }
    if (lane == 31) { qR.x = 0.f; qR.y = 0.f; qR.z = 0.f; qR.w = 0.f; }

    ull A0 = pk(a.x, a.y);
    ull A1 = pk(a.z, a.w);

    // f[0..11] = in2[x0-4 .. x0+7] = qL | m | qR
    ull E[6], O[5];
    E[0] = pk(qL.x, qL.y); E[1] = pk(qL.z, qL.w);
    E[2] = pk(m.x,  m.y ); E[3] = pk(m.z,  m.w );
    E[4] = pk(qR.x, qR.y); E[5] = pk(qR.z, qR.w);
    O[0] = pk(qL.y, qL.z); O[1] = pk(qL.w, m.x );
    O[2] = pk(m.y,  m.z ); O[3] = pk(m.w,  qR.x);
    O[4] = pk(qR.y, qR.z);

#pragma unroll
    for (int d = 0; d < 9; d++) {
        ull b0 = (d & 1) ? O[(d >> 1)]     : E[(d >> 1)];
        ull b1 = (d & 1) ? O[(d >> 1) + 1] : E[(d >> 1) + 1];
        ffma2(acc[d][0], A0, b0);
        ffma2(acc[d][1], A1, b1);
    }
}

__global__ void __launch_bounds__(THREADS, 2)
corr_kernel(const float* __restrict__ in1, const float* __restrict__ in2,
            float* __restrict__ out)
{
    const int tid  = threadIdx.x;
    const int warp = tid >> 5;         // dy 0..8
    const int lane = tid & 31;
    const int x0   = lane << 2;        // 4 px per lane

    const int bx = blockIdx.x;
    const int b  = bx / HH;
    const int h0 = bx - b * HH;        // output row

    const int hB = h0 + warp - 4;      // this warp's in2 source row
    const bool rowOK = (hB >= 0) && (hB < HH);   // warp-uniform

    ull acc[9][2];
#pragma unroll
    for (int d = 0; d < 9; d++) { acc[d][0] = 0ull; acc[d][1] = 0ull; }

    if (rowOK) {
        const float4* pA = (const float4*)(in1 + (size_t)(b * CTOT) * CHS + h0 * WW + x0);
        const float4* pB = (const float4*)(in2 + (size_t)(b * CTOT) * CHS + hB * WW + x0);

        // Software pipeline on B: distance-2 register prefetch (named slots).
        float4 m0 = __ldg(pB);
        float4 m1 = __ldg(pB + CHS4);

        for (int c = 0; c < CTOT - 2; c += 2) {
            float4 m2 = __ldg(pB + (size_t)(c + 2) * CHS4);
            float4 m3 = __ldg(pB + (size_t)(c + 3) * CHS4);
            float4 a0 = __ldg(pA + (size_t)c * CHS4);
            float4 a1 = __ldg(pA + (size_t)(c + 1) * CHS4);
            compute_channel(a0, m0, lane, acc);
            compute_channel(a1, m1, lane, acc);
            m0 = m2;
            m1 = m3;
        }
        // Tail: channels CTOT-2, CTOT-1
        {
            float4 a0 = __ldg(pA + (size_t)(CTOT - 2) * CHS4);
            float4 a1 = __ldg(pA + (size_t)(CTOT - 1) * CHS4);
            compute_channel(a0, m0, lane, acc);
            compute_channel(a1, m1, lane, acc);
        }
    }

    // Epilogue: out[b, warp*9+d, h0, x0..x0+3] = acc / 256  (zeros when !rowOK)
    const float inv = 1.0f / 256.0f;
#pragma unroll
    for (int d = 0; d < 9; d++) {
        const int n = warp * 9 + d;
        float* op = out + ((size_t)((b * 81 + n) * HH + h0)) * WW + x0;
        float2 u0 = upk(acc[d][0]);
        float2 u1 = upk(acc[d][1]);
        *(float4*)op = make_float4(u0.x * inv, u0.y * inv, u1.x * inv, u1.y * inv);
    }
}

extern "C" void kernel_launch(void* const* d_in, const int* in_sizes, int n_in,
                              void* d_out, int out_size)
{
    const float* in1 = (const float*)d_in[0];
    const float* in2 = (const float*)d_in[1];
    float* out = (float*)d_out;

    corr_kernel<<<BB * HH, THREADS>>>(in1, in2, out);
}

// round 12
// speedup vs baseline: 2.3279x; 1.0855x over previous
#include <cuda_runtime.h>
#include <cstdint>

#define BB      8
#define CTOT    256
#define HH      96
#define WW      128
#define CCK     4                  // channels per chunk
#define NCHUNK  (CTOT/CCK)         // 64
#define NBUF    3                  // ring buffers
#define DEPTH   2                  // prefetch distance (chunks)
#define THREADS 288                // 9 warps, one dy each
#define CHS     (HH*WW)            // channel stride (floats)
#define CHS4    (CHS/4)

#define ROWB       512                         // bytes per row (128 floats, no halo)
#define WARP_SEG   (CCK*ROWB)                  // 2048 per warp per buffer
#define BUF_BYTES  (9*WARP_SEG)                // 18432
#define SMEM_TOTAL (NBUF*BUF_BYTES)            // 55296 -> 3 blocks/SM

typedef unsigned long long ull;

__device__ __forceinline__ float4 lds128(uint32_t addr) {
    float4 v;
    asm volatile("ld.shared.v4.f32 {%0,%1,%2,%3}, [%4];"
                 : "=f"(v.x), "=f"(v.y), "=f"(v.z), "=f"(v.w) : "r"(addr));
    return v;
}
__device__ __forceinline__ void cpa16(uint32_t dst, const float* src) {
    asm volatile("cp.async.cg.shared.global [%0], [%1], 16;" :: "r"(dst), "l"(src));
}
__device__ __forceinline__ ull pk(float lo, float hi) {
    ull r;
    asm("mov.b64 %0, {%1,%2};" : "=l"(r) : "f"(lo), "f"(hi));
    return r;
}
__device__ __forceinline__ float2 upk(ull v) {
    float2 f;
    asm("mov.b64 {%0,%1}, %2;" : "=f"(f.x), "=f"(f.y) : "l"(v));
    return f;
}
__device__ __forceinline__ void ffma2(ull& d, ull a, ull b) {
    asm("fma.rn.f32x2 %0, %1, %2, %0;" : "+l"(d) : "l"(a), "l"(b));
}

// Warp-private loader: lane's own quad for CCK channels. No pads, no halo.
__device__ __forceinline__ void load_chunk(uint32_t wbuf, const float* src, int lane)
{
    const uint32_t dst0 = wbuf + (uint32_t)(lane * 16);
    const float* s = src + lane * 4;
#pragma unroll
    for (int c = 0; c < CCK; c++)
        cpa16(dst0 + c * ROWB, s + (size_t)c * CHS);
    asm volatile("cp.async.commit_group;" ::: "memory");
}

// One channel: m from smem, halo via shuffles, 18 packed FMAs.
__device__ __forceinline__ void compute_channel(float4 a, float4 m, int lane,
                                                ull acc[9][2])
{
    float4 qL, qR;
    qL.x = __shfl_up_sync(0xffffffffu, m.x, 1);
    qL.y = __shfl_up_sync(0xffffffffu, m.y, 1);
    qL.z = __shfl_up_sync(0xffffffffu, m.z, 1);
    qL.w = __shfl_up_sync(0xffffffffu, m.w, 1);
    qR.x = __shfl_down_sync(0xffffffffu, m.x, 1);
    qR.y = __shfl_down_sync(0xffffffffu, m.y, 1);
    qR.z = __shfl_down_sync(0xffffffffu, m.z, 1);
    qR.w = __shfl_down_sync(0xffffffffu, m.w, 1);
    if (lane == 0)  { qL.x = 0.f; qL.y = 0.f; qL.z = 0.f; qL.w = 0.f; }
    if (lane == 31) { qR.x = 0.f; qR.y = 0.f; qR.z = 0.f; qR.w = 0.f; }

    ull A0 = pk(a.x, a.y);
    ull A1 = pk(a.z, a.w);

    // f[0..11] = in2[x0-4 .. x0+7] = qL | m | qR
    ull E[6], O[5];
    E[0] = pk(qL.x, qL.y); E[1] = pk(qL.z, qL.w);
    E[2] = pk(m.x,  m.y ); E[3] = pk(m.z,  m.w );
    E[4] = pk(qR.x, qR.y); E[5] = pk(qR.z, qR.w);
    O[0] = pk(qL.y, qL.z); O[1] = pk(qL.w, m.x );
    O[2] = pk(m.y,  m.z ); O[3] = pk(m.w,  qR.x);
    O[4] = pk(qR.y, qR.z);

#pragma unroll
    for (int d = 0; d < 9; d++) {
        ull b0 = (d & 1) ? O[(d >> 1)]     : E[(d >> 1)];
        ull b1 = (d & 1) ? O[(d >> 1) + 1] : E[(d >> 1) + 1];
        ffma2(acc[d][0], A0, b0);
        ffma2(acc[d][1], A1, b1);
    }
}

__global__ void __launch_bounds__(THREADS, 3)
corr_kernel(const float* __restrict__ in1, const float* __restrict__ in2,
            float* __restrict__ out)
{
    extern __shared__ char smem[];
    const uint32_t smem32 = (uint32_t)__cvta_generic_to_shared(smem);

    const int tid  = threadIdx.x;
    const int warp = tid >> 5;         // dy 0..8
    const int lane = tid & 31;
    const int x0   = lane << 2;        // 4 px per lane

    const int bx = blockIdx.x;
    const int b  = bx / HH;
    const int h0 = bx - b * HH;        // output row

    const int hB = h0 + warp - 4;      // this warp's in2 source row
    const bool rowOK = (hB >= 0) && (hB < HH);   // warp-uniform

    ull acc[9][2];
#pragma unroll
    for (int d = 0; d < 9; d++) { acc[d][0] = 0ull; acc[d][1] = 0ull; }

    if (rowOK) {
        const uint32_t wbBase = smem32 + (uint32_t)(warp * WARP_SEG);
        const uint32_t wbEnd  = wbBase + SMEM_TOTAL;
        const uint32_t mAddr0 = (uint32_t)(lane * 16);

        const float4* pA = (const float4*)(in1 + (size_t)(b * CTOT) * CHS + h0 * WW + x0);
        const float*  sp = in2 + (size_t)(b * CTOT) * CHS + hB * WW;
        const size_t CSTEP = (size_t)CCK * CHS;

        // Prologue: fill DEPTH buffers
        uint32_t wbNxt = wbBase;
#pragma unroll
        for (int i = 0; i < DEPTH; i++) {
            load_chunk(wbNxt, sp, lane);
            sp += CSTEP;
            wbNxt += BUF_BYTES;
        }
        uint32_t wbCur = wbBase;

        for (int k = 0; k < NCHUNK; k++) {
            if (k + DEPTH < NCHUNK) {
                load_chunk(wbNxt, sp, lane);
                sp += CSTEP;
                wbNxt += BUF_BYTES;
                if (wbNxt >= wbEnd) wbNxt -= SMEM_TOTAL;
                asm volatile("cp.async.wait_group 2;" ::: "memory");
            } else if (k + 1 < NCHUNK) {
                asm volatile("cp.async.wait_group 1;" ::: "memory");
            } else {
                asm volatile("cp.async.wait_group 0;" ::: "memory");
            }
#pragma unroll
            for (int cc = 0; cc < CCK; cc++) {
                float4 m = lds128(wbCur + cc * ROWB + mAddr0);
                float4 a = __ldg(pA + (size_t)(k * CCK + cc) * CHS4);
                compute_channel(a, m, lane, acc);
            }
            wbCur += BUF_BYTES;
            if (wbCur >= wbEnd) wbCur -= SMEM_TOTAL;
        }
    }

    // Epilogue: out[b, warp*9+d, h0, x0..x0+3] = acc / 256  (zeros when !rowOK)
    const float inv = 1.0f / 256.0f;
#pragma unroll
    for (int d = 0; d < 9; d++) {
        const int n = warp * 9 + d;
        float* op = out + ((size_t)((b * 81 + n) * HH + h0)) * WW + x0;
        float2 u0 = upk(acc[d][0]);
        float2 u1 = upk(acc[d][1]);
        *(float4*)op = make_float4(u0.x * inv, u0.y * inv, u1.x * inv, u1.y * inv);
    }
}

extern "C" void kernel_launch(void* const* d_in, const int* in_sizes, int n_in,
                              void* d_out, int out_size)
{
    const float* in1 = (const float*)d_in[0];
    const float* in2 = (const float*)d_in[1];
    float* out = (float*)d_out;

    cudaFuncSetAttribute(corr_kernel, cudaFuncAttributeMaxDynamicSharedMemorySize, SMEM_TOTAL);
    corr_kernel<<<BB * HH, THREADS, SMEM_TOTAL>>>(in1, in2, out);
}